// round 8
// baseline (speedup 1.0000x reference)
#include <cuda_runtime.h>

// ODELinear: 96 RK4(3/8) trajectory pairs, 192 persistent CTAs (pair x half),
// LPT by bid. Inner tile 8 rows x 4 cols: f32x2 FMAs with zero packing overhead
// (row-pairs naturally packed via transposed state; weights duplicated (w,w)),
// skewed conflict-free smem layout with compile-time offsets.

#define Lg 96
#define Hh 8
#define E 64
#define EH 128
#define NT 256
#define RS 92
#define IDX(r) ((r) + (((r) >> 3) << 2))

typedef unsigned long long ull;

struct __align__(16) Smem {
    float tmpT[E][RS];   // stage input / state, transposed [feature][skewed row]
    float HT[EH][RS];    // hidden activations
    float2 W1d[E][EH];   // duplicated-lane weights (w,w)
    float2 W2d[EH][E];
    float2 b1d[EH];
    float2 b2d[E];
    float Ts[Lg];
};

__device__ __forceinline__ float tanh_fast(float x) {
    // 1 - 2/(e^{2x}+1): exact at saturation, rel err ~1e-6
    float e = __expf(2.0f * x);
    return 1.0f - __fdividef(2.0f, e + 1.0f);
}

__device__ __forceinline__ ull fma2(ull a, ull b, ull c) {
    ull d;
    asm("fma.rn.f32x2 %0, %1, %2, %3;" : "=l"(d) : "l"(a), "l"(b), "l"(c));
    return d;
}
__device__ __forceinline__ void unpack2(ull v, float& lo, float& hi) {
    asm("mov.b64 {%0, %1}, %2;" : "=f"(lo), "=f"(hi) : "l"(v));
}
__device__ __forceinline__ float4 ld4(const float* p) { return *(const float4*)p; }
__device__ __forceinline__ void st4(float* p, float4 v) { *(float4*)p = v; }

__global__ void __launch_bounds__(NT, 1)
ode_kernel(const float* __restrict__ x, const float* __restrict__ Tg,
           const float* __restrict__ W1g, const float* __restrict__ b1g,
           const float* __restrict__ W2g, const float* __restrict__ b2g,
           float2* __restrict__ out) {
    extern __shared__ char smraw[];
    Smem* s = (Smem*)smraw;
    const int tid = threadIdx.x;
    const int pi = blockIdx.x >> 1;   // pair index 0..95, descending work => LPT
    const int half = blockIdx.x & 1;  // which 32-row (b,h) half
    const int trajF = pi;
    const int trajB = 95 - pi;

    // --- weights (duplicated lanes), biases, timeslots ---
    for (int t = tid; t < E * EH; t += NT) {
        float w = W1g[t];
        ((float2*)s->W1d)[t] = make_float2(w, w);
    }
    for (int t = tid; t < EH * E; t += NT) {
        float w = W2g[t];
        ((float2*)s->W2d)[t] = make_float2(w, w);
    }
    if (tid < EH) { float w = b1g[tid]; s->b1d[tid] = make_float2(w, w); }
    if (tid < E)  { float w = b2g[tid]; s->b2d[tid] = make_float2(w, w); }
    if (tid < Lg) s->Ts[tid] = Tg[tid];

    // --- initial states: rows 0..31 = fwd traj half, 32..63 = bwd traj half ---
    for (int t = tid; t < 64 * E; t += NT) {
        int u = t >> 6, e = t & 63;
        int traj = (u < 32) ? trajF : trajB;
        int grow = half * 32 + (u & 31);
        int b = grow >> 3, h = grow & 7;
        s->tmpT[e][IDX(u)] = x[(((b * Lg + traj) * Hh + h) << 6) + e];
    }
    __syncthreads();

    const int rg = tid & 7;
    const int r0 = rg * 8;     // 8-row block origin (0..56)
    const int cg = tid >> 3;   // 0..31
    const int c0 = cg * 4;     // GEMM1 column base (0..124)
    const int c2 = cg * 2;     // GEMM2 column base (0..62)

    // persistent register tiles [col 0..1][row 0..7] for GEMM2 cols c2.., rows r0..
    float yt[2][8], x0t[2][8], Pt[2][8], Qt[2][8];
#pragma unroll
    for (int c = 0; c < 2; ++c) {
        float4 lo = ld4(&s->tmpT[c2 + c][IDX(r0)]);
        float4 hi = ld4(&s->tmpT[c2 + c][IDX(r0) + 4]);
        yt[c][0] = x0t[c][0] = lo.x; yt[c][1] = x0t[c][1] = lo.y;
        yt[c][2] = x0t[c][2] = lo.z; yt[c][3] = x0t[c][3] = lo.w;
        yt[c][4] = x0t[c][4] = hi.x; yt[c][5] = x0t[c][5] = hi.y;
        yt[c][6] = x0t[c][6] = hi.z; yt[c][7] = x0t[c][7] = hi.w;
    }

    // emission base: rows r0..r0+7 share b; h == row offset r
    const int myTraj = (r0 < 32) ? trajF : trajB;
    const int growBase = half * 32 + (r0 & 31);
    const int bIdx = growBase >> 3;
    float2* const obase =
        out + (size_t)(bIdx * Lg + myTraj) * (Lg * Hh * 64) + c2;

    // diagonal emission j == trajF (fwd rows only; every traj covered once)
    if (r0 < 32) {
#pragma unroll
        for (int r = 0; r < 8; ++r) {
            float4* p = (float4*)(obase + (size_t)trajF * (Hh * 64) + r * 64);
            *p = make_float4(x0t[0][r], x0t[0][r], x0t[1][r], x0t[1][r]);
        }
    }

    int jcur = (r0 < 32) ? (pi + 1) : (94 - pi);
    const int jd = (r0 < 32) ? 1 : -1;

    const int len = 95 - pi;  // identical for both batched trajectories
    for (int n = 0; n < len; ++n) {
        const float dt_f = s->Ts[pi + n + 1] - s->Ts[pi + n];
        const float dt_b = s->Ts[94 - pi - n] - s->Ts[95 - pi - n];  // negative
        const float dt = (r0 < 32) ? dt_f : dt_b;

#pragma unroll 1
        for (int m = 0; m < 4; ++m) {
            // ---- GEMM1: H = tanh(src @ W1 + b1); 8 rows x 4 cols per thread ----
            ull acc[4][4];
            {
                ulonglong2 bb0 = *(const ulonglong2*)&s->b1d[c0];
                ulonglong2 bb1 = *(const ulonglong2*)&s->b1d[c0 + 2];
#pragma unroll
                for (int rp = 0; rp < 4; ++rp) {
                    acc[0][rp] = bb0.x; acc[1][rp] = bb0.y;
                    acc[2][rp] = bb1.x; acc[3][rp] = bb1.y;
                }
            }
#pragma unroll 8
            for (int k = 0; k < E; ++k) {
                const ulonglong2* sp = (const ulonglong2*)&s->tmpT[k][IDX(r0)];
                ulonglong2 sA = sp[0], sB = sp[1];   // 4 packed row-pairs
                const ulonglong2* wp = (const ulonglong2*)&s->W1d[k][c0];
                ulonglong2 wA = wp[0], wB = wp[1];   // 4 dup cols
                acc[0][0] = fma2(wA.x, sA.x, acc[0][0]);
                acc[0][1] = fma2(wA.x, sA.y, acc[0][1]);
                acc[0][2] = fma2(wA.x, sB.x, acc[0][2]);
                acc[0][3] = fma2(wA.x, sB.y, acc[0][3]);
                acc[1][0] = fma2(wA.y, sA.x, acc[1][0]);
                acc[1][1] = fma2(wA.y, sA.y, acc[1][1]);
                acc[1][2] = fma2(wA.y, sB.x, acc[1][2]);
                acc[1][3] = fma2(wA.y, sB.y, acc[1][3]);
                acc[2][0] = fma2(wB.x, sA.x, acc[2][0]);
                acc[2][1] = fma2(wB.x, sA.y, acc[2][1]);
                acc[2][2] = fma2(wB.x, sB.x, acc[2][2]);
                acc[2][3] = fma2(wB.x, sB.y, acc[2][3]);
                acc[3][0] = fma2(wB.y, sA.x, acc[3][0]);
                acc[3][1] = fma2(wB.y, sA.y, acc[3][1]);
                acc[3][2] = fma2(wB.y, sB.x, acc[3][2]);
                acc[3][3] = fma2(wB.y, sB.y, acc[3][3]);
            }
#pragma unroll
            for (int c = 0; c < 4; ++c) {
                float v[8];
#pragma unroll
                for (int rp = 0; rp < 4; ++rp)
                    unpack2(acc[c][rp], v[2 * rp], v[2 * rp + 1]);
                st4(&s->HT[c0 + c][IDX(r0)],
                    make_float4(tanh_fast(v[0]), tanh_fast(v[1]),
                                tanh_fast(v[2]), tanh_fast(v[3])));
                st4(&s->HT[c0 + c][IDX(r0) + 4],
                    make_float4(tanh_fast(v[4]), tanh_fast(v[5]),
                                tanh_fast(v[6]), tanh_fast(v[7])));
            }
            __syncthreads();

            // ---- GEMM2: K = H @ W2 + b2; 8 rows x 2 cols per thread ----
            ull a2[2][4];
            {
                ulonglong2 bb = *(const ulonglong2*)&s->b2d[c2];
#pragma unroll
                for (int rp = 0; rp < 4; ++rp) { a2[0][rp] = bb.x; a2[1][rp] = bb.y; }
            }
#pragma unroll 8
            for (int k = 0; k < EH; ++k) {
                const ulonglong2* hp = (const ulonglong2*)&s->HT[k][IDX(r0)];
                ulonglong2 hA = hp[0], hB = hp[1];
                ulonglong2 wv = *(const ulonglong2*)&s->W2d[k][c2];
                a2[0][0] = fma2(wv.x, hA.x, a2[0][0]);
                a2[0][1] = fma2(wv.x, hA.y, a2[0][1]);
                a2[0][2] = fma2(wv.x, hB.x, a2[0][2]);
                a2[0][3] = fma2(wv.x, hB.y, a2[0][3]);
                a2[1][0] = fma2(wv.y, hA.x, a2[1][0]);
                a2[1][1] = fma2(wv.y, hA.y, a2[1][1]);
                a2[1][2] = fma2(wv.y, hB.x, a2[1][2]);
                a2[1][3] = fma2(wv.y, hB.y, a2[1][3]);
            }
            float kv[2][8];
#pragma unroll
            for (int c = 0; c < 2; ++c)
#pragma unroll
                for (int rp = 0; rp < 4; ++rp)
                    unpack2(a2[c][rp], kv[c][2 * rp], kv[c][2 * rp + 1]);

            // ---- fused RK4 stage combine (P = k1-k2, Q = k1+3k2+3k3) ----
            if (m == 0) {
#pragma unroll
                for (int c = 0; c < 2; ++c) {
                    float t[8];
#pragma unroll
                    for (int r = 0; r < 8; ++r) {
                        Pt[c][r] = kv[c][r];
                        Qt[c][r] = kv[c][r];
                        t[r] = fmaf(dt * (1.0f / 3.0f), kv[c][r], yt[c][r]);
                    }
                    st4(&s->tmpT[c2 + c][IDX(r0)], make_float4(t[0], t[1], t[2], t[3]));
                    st4(&s->tmpT[c2 + c][IDX(r0) + 4], make_float4(t[4], t[5], t[6], t[7]));
                }
            } else if (m == 1) {
#pragma unroll
                for (int c = 0; c < 2; ++c) {
                    float t[8];
#pragma unroll
                    for (int r = 0; r < 8; ++r) {
                        // y3 = y + dt*k2 - (dt/3)*k1
                        t[r] = fmaf(dt, kv[c][r],
                                    fmaf(-dt * (1.0f / 3.0f), Pt[c][r], yt[c][r]));
                        Qt[c][r] = fmaf(3.0f, kv[c][r], Qt[c][r]);  // k1 + 3k2
                        Pt[c][r] = Pt[c][r] - kv[c][r];             // k1 - k2
                    }
                    st4(&s->tmpT[c2 + c][IDX(r0)], make_float4(t[0], t[1], t[2], t[3]));
                    st4(&s->tmpT[c2 + c][IDX(r0) + 4], make_float4(t[4], t[5], t[6], t[7]));
                }
            } else if (m == 2) {
#pragma unroll
                for (int c = 0; c < 2; ++c) {
                    float t[8];
#pragma unroll
                    for (int r = 0; r < 8; ++r) {
                        // y4 = y + dt*(k1 - k2 + k3)
                        t[r] = fmaf(dt, Pt[c][r] + kv[c][r], yt[c][r]);
                        Qt[c][r] = fmaf(3.0f, kv[c][r], Qt[c][r]);  // + 3k3
                    }
                    st4(&s->tmpT[c2 + c][IDX(r0)], make_float4(t[0], t[1], t[2], t[3]));
                    st4(&s->tmpT[c2 + c][IDX(r0) + 4], make_float4(t[4], t[5], t[6], t[7]));
                }
            } else {
#pragma unroll
                for (int c = 0; c < 2; ++c) {
#pragma unroll
                    for (int r = 0; r < 8; ++r)
                        yt[c][r] = fmaf(dt * 0.125f, Qt[c][r] + kv[c][r], yt[c][r]);
                    st4(&s->tmpT[c2 + c][IDX(r0)],
                        make_float4(yt[c][0], yt[c][1], yt[c][2], yt[c][3]));
                    st4(&s->tmpT[c2 + c][IDX(r0) + 4],
                        make_float4(yt[c][4], yt[c][5], yt[c][6], yt[c][7]));
                }
                // fused emission from registers (h == r for this thread's rows)
#pragma unroll
                for (int r = 0; r < 8; ++r) {
                    float4* p = (float4*)(obase + (size_t)jcur * (Hh * 64) + r * 64);
                    *p = make_float4(x0t[0][r], yt[0][r], x0t[1][r], yt[1][r]);
                }
            }
            __syncthreads();
        }
        jcur += jd;
    }
}

extern "C" void kernel_launch(void* const* d_in, const int* in_sizes, int n_in,
                              void* d_out, int out_size) {
    (void)in_sizes; (void)n_in; (void)out_size;
    cudaFuncSetAttribute(ode_kernel, cudaFuncAttributeMaxDynamicSharedMemorySize,
                         (int)sizeof(Smem));
    ode_kernel<<<192, NT, sizeof(Smem)>>>(
        (const float*)d_in[0], (const float*)d_in[1], (const float*)d_in[2],
        (const float*)d_in[3], (const float*)d_in[4], (const float*)d_in[5],
        (float2*)d_out);
}

// round 11
// speedup vs baseline: 2.0186x; 2.0186x over previous
#include <cuda_runtime.h>
#include <cuda_bf16.h>
#include <cstdint>

// ODELinear via mma.sync (HMMA, bf16 hi/lo 3-term split, fp32 accum).
// One CTA per trajectory pair: rows 0..63 = fwd traj pi, 64..127 = bwd traj 95-pi.
// 96 CTAs (single wave), 256 threads; warp w owns rows 16w..16w+15 (w<4 fwd,
// w>=4 bwd). H intermediate + RK4 stage state are register-resident via
// matching D->A fragment mappings; no __syncthreads in the main loop.

#define Lg 96
#define Hh 8
#define NT 256

struct __align__(16) Smem {
    uint4 W1F[4][16][32];   // GEMM1 B-frags: [k-chunk][n-chunk][lane] = {b0h,b1h,b0l,b1l}
    uint4 W2F[8][8][32];    // GEMM2 B-frags
    float4 x0s[8][256];     // per-thread x0 values at D2 positions
    float Ts[Lg];
    float b1s[128];
    float b2s[64];
};

__device__ __forceinline__ uint32_t packbf(float a, float b) {  // lo=a, hi=b
    uint32_t r;
    asm("cvt.rn.bf16x2.f32 %0, %1, %2;" : "=r"(r) : "f"(b), "f"(a));
    return r;
}
__device__ __forceinline__ void split2(float a, float b, uint32_t& hi, uint32_t& lo) {
    hi = packbf(a, b);
    float fa = __uint_as_float(hi << 16);
    float fb = __uint_as_float(hi & 0xFFFF0000u);
    lo = packbf(a - fa, b - fb);
}
__device__ __forceinline__ float tanh_fast(float x) {
    // 1 - 2/(e^{2x}+1): exact at saturation, rel err ~1e-6
    float e = __expf(2.0f * x);
    return 1.0f - __fdividef(2.0f, e + 1.0f);
}

#define MMA(d, a, b0, b1)                                                     \
    asm volatile(                                                             \
        "mma.sync.aligned.m16n8k16.row.col.f32.bf16.bf16.f32 "                \
        "{%0,%1,%2,%3},{%4,%5,%6,%7},{%8,%9},{%0,%1,%2,%3};"                  \
        : "+f"((d)[0]), "+f"((d)[1]), "+f"((d)[2]), "+f"((d)[3])              \
        : "r"((a)[0]), "r"((a)[1]), "r"((a)[2]), "r"((a)[3]), "r"(b0), "r"(b1))

__global__ void __launch_bounds__(NT, 1)
ode_kernel(const float* __restrict__ x, const float* __restrict__ Tg,
           const float* __restrict__ W1g, const float* __restrict__ b1g,
           const float* __restrict__ W2g, const float* __restrict__ b2g,
           float* __restrict__ out) {
    extern __shared__ __align__(16) char smraw[];
    Smem* s = (Smem*)smraw;
    const int tid = threadIdx.x;
    const int lane = tid & 31;
    const int w = tid >> 5;
    const int gr = lane >> 2;  // fragment "group row" 0..7
    const int tg = lane & 3;   // fragment "thread in group" 0..3
    const int pi = blockIdx.x;
    const int trajF = pi, trajB = 95 - pi;
    const int len = 95 - pi;

    // ---- weight fragment prep (once) ----
    for (int idx = tid; idx < 2048; idx += NT) {
        int ln = idx & 31, nc = (idx >> 5) & 15, kc = idx >> 9;
        int g2 = ln >> 2, t2 = ln & 3;
        int k0 = kc * 16 + t2 * 2, nn = nc * 8 + g2;
        float w00 = W1g[k0 * 128 + nn], w01 = W1g[(k0 + 1) * 128 + nn];
        float w10 = W1g[(k0 + 8) * 128 + nn], w11 = W1g[(k0 + 9) * 128 + nn];
        uint32_t h0, l0, h1, l1;
        split2(w00, w01, h0, l0);
        split2(w10, w11, h1, l1);
        s->W1F[kc][nc][ln] = make_uint4(h0, h1, l0, l1);
    }
    for (int idx = tid; idx < 2048; idx += NT) {
        int ln = idx & 31, nc = (idx >> 5) & 7, kc = idx >> 8;
        int g2 = ln >> 2, t2 = ln & 3;
        int k0 = kc * 16 + t2 * 2, nn = nc * 8 + g2;
        float w00 = W2g[k0 * 64 + nn], w01 = W2g[(k0 + 1) * 64 + nn];
        float w10 = W2g[(k0 + 8) * 64 + nn], w11 = W2g[(k0 + 9) * 64 + nn];
        uint32_t h0, l0, h1, l1;
        split2(w00, w01, h0, l0);
        split2(w10, w11, h1, l1);
        s->W2F[kc][nc][ln] = make_uint4(h0, h1, l0, l1);
    }
    if (tid < 128) s->b1s[tid] = b1g[tid];
    if (tid < 64) s->b2s[tid] = b2g[tid];
    if (tid < Lg) s->Ts[tid] = Tg[tid];

    // ---- per-thread rows: ra = 16w+gr, rb = ra+8 (same stripe, same traj) ----
    const bool fwd = (w < 4);
    const int traj = fwd ? trajF : trajB;
    const int ra = w * 16 + gr;
    const int ga = ra & 63, gb = ga + 8;
    const int bA = ga >> 3, hA = ga & 7;
    const int bB = gb >> 3, hB = gb & 7;
    const float* pA = x + (((bA * Lg + traj) * Hh + hA) << 6);
    const float* pB = x + (((bB * Lg + traj) * Hh + hB) << 6);

    // persistent state at D2 positions: rows {gr, gr+8} of stripe, cols {8*nc2+2tg, +1}
    float yt[8][4], Pt[8][4], Qt[8][4];
#pragma unroll
    for (int nc2 = 0; nc2 < 8; ++nc2) {
        int c = nc2 * 8 + tg * 2;
        float2 va = *(const float2*)(pA + c);
        float2 vb = *(const float2*)(pB + c);
        yt[nc2][0] = va.x; yt[nc2][1] = va.y;
        yt[nc2][2] = vb.x; yt[nc2][3] = vb.y;
        s->x0s[nc2][tid] = make_float4(va.x, va.y, vb.x, vb.y);
    }

    // A-fragments of the current stage input (hi/lo), register-resident
    uint32_t Ah[4][4], Al[4][4];
#pragma unroll
    for (int kc = 0; kc < 4; ++kc) {
        split2(yt[2 * kc][0], yt[2 * kc][1], Ah[kc][0], Al[kc][0]);
        split2(yt[2 * kc][2], yt[2 * kc][3], Ah[kc][1], Al[kc][1]);
        split2(yt[2 * kc + 1][0], yt[2 * kc + 1][1], Ah[kc][2], Al[kc][2]);
        split2(yt[2 * kc + 1][2], yt[2 * kc + 1][3], Ah[kc][3], Al[kc][3]);
    }

    // output bases (float indices); element (b,i,j,h,e,2)
    float* obA = out + (size_t)(bA * Lg + traj) * 98304 + hA * 128 + tg * 4;
    float* obB = out + (size_t)(bB * Lg + traj) * 98304 + hB * 128 + tg * 4;

    __syncthreads();  // weights/biases ready

    // diagonal emission j == trajF (fwd warps only; covers every traj once)
    if (fwd) {
#pragma unroll
        for (int nc2 = 0; nc2 < 8; ++nc2) {
            *(float4*)(obA + (size_t)trajF * 1024 + nc2 * 16) =
                make_float4(yt[nc2][0], yt[nc2][0], yt[nc2][1], yt[nc2][1]);
            *(float4*)(obB + (size_t)trajF * 1024 + nc2 * 16) =
                make_float4(yt[nc2][2], yt[nc2][2], yt[nc2][3], yt[nc2][3]);
        }
    }

    const float* Ts = s->Ts;
    for (int n = 0; n < len; ++n) {
        const float dt = fwd ? (Ts[pi + n + 1] - Ts[pi + n])
                             : (Ts[94 - pi - n] - Ts[95 - pi - n]);  // negative
        const int j = fwd ? (pi + n + 1) : (94 - pi - n);

#pragma unroll 1
        for (int m = 0; m < 4; ++m) {
            uint32_t A2h[8][4], A2l[8][4];

            // ---- GEMM1: H = tanh(Y @ W1 + b1), two n-halves ----
#pragma unroll 1
            for (int half = 0; half < 2; ++half) {
                float acc[8][4];
#pragma unroll
                for (int a = 0; a < 8; ++a)
#pragma unroll
                    for (int b = 0; b < 4; ++b) acc[a][b] = 0.0f;

#pragma unroll
                for (int kc = 0; kc < 4; ++kc) {
#pragma unroll
                    for (int ncl = 0; ncl < 8; ++ncl) {
                        uint4 wv = s->W1F[kc][half * 8 + ncl][lane];
                        MMA(acc[ncl], Ah[kc], wv.x, wv.y);
                        MMA(acc[ncl], Ah[kc], wv.z, wv.w);
                        MMA(acc[ncl], Al[kc], wv.x, wv.y);
                    }
                }
                // epilogue 1: bias + tanh -> A2 fragments (register-local D->A)
#pragma unroll
                for (int p = 0; p < 4; ++p) {
                    const int kc2 = half * 4 + p;
                    const int cb = (half * 8 + 2 * p) * 8 + tg * 2;
                    float2 b1a = *(const float2*)&s->b1s[cb];
                    float2 b1b = *(const float2*)&s->b1s[cb + 8];
                    float t00 = tanh_fast(acc[2 * p][0] + b1a.x);
                    float t01 = tanh_fast(acc[2 * p][1] + b1a.y);
                    float t02 = tanh_fast(acc[2 * p][2] + b1a.x);
                    float t03 = tanh_fast(acc[2 * p][3] + b1a.y);
                    float t10 = tanh_fast(acc[2 * p + 1][0] + b1b.x);
                    float t11 = tanh_fast(acc[2 * p + 1][1] + b1b.y);
                    float t12 = tanh_fast(acc[2 * p + 1][2] + b1b.x);
                    float t13 = tanh_fast(acc[2 * p + 1][3] + b1b.y);
                    split2(t00, t01, A2h[kc2][0], A2l[kc2][0]);
                    split2(t02, t03, A2h[kc2][1], A2l[kc2][1]);
                    split2(t10, t11, A2h[kc2][2], A2l[kc2][2]);
                    split2(t12, t13, A2h[kc2][3], A2l[kc2][3]);
                }
            }

            // ---- GEMM2: K = H @ W2 + b2 ----
            float acc2[8][4];
#pragma unroll
            for (int a = 0; a < 8; ++a)
#pragma unroll
                for (int b = 0; b < 4; ++b) acc2[a][b] = 0.0f;
#pragma unroll
            for (int kc2 = 0; kc2 < 8; ++kc2) {
#pragma unroll
                for (int nc2 = 0; nc2 < 8; ++nc2) {
                    uint4 wv = s->W2F[kc2][nc2][lane];
                    MMA(acc2[nc2], A2h[kc2], wv.x, wv.y);
                    MMA(acc2[nc2], A2h[kc2], wv.z, wv.w);
                    MMA(acc2[nc2], A2l[kc2], wv.x, wv.y);
                }
            }

            // ---- epilogue 2: RK4 combine (P=k1-k2, Q=k1+3k2+3k3), rebuild A ----
            float stv[8][4];
#pragma unroll
            for (int nc2 = 0; nc2 < 8; ++nc2) {
                int c = nc2 * 8 + tg * 2;
                float2 b2v = *(const float2*)&s->b2s[c];
#pragma unroll
                for (int i = 0; i < 4; ++i) {
                    float kv = acc2[nc2][i] + ((i & 1) ? b2v.y : b2v.x);
                    if (m == 0) {
                        Pt[nc2][i] = kv;
                        Qt[nc2][i] = kv;
                        stv[nc2][i] = fmaf(dt * (1.0f / 3.0f), kv, yt[nc2][i]);
                    } else if (m == 1) {
                        stv[nc2][i] = fmaf(dt, kv,
                                           fmaf(-dt * (1.0f / 3.0f), Pt[nc2][i], yt[nc2][i]));
                        Qt[nc2][i] = fmaf(3.0f, kv, Qt[nc2][i]);
                        Pt[nc2][i] = Pt[nc2][i] - kv;
                    } else if (m == 2) {
                        stv[nc2][i] = fmaf(dt, Pt[nc2][i] + kv, yt[nc2][i]);
                        Qt[nc2][i] = fmaf(3.0f, kv, Qt[nc2][i]);
                    } else {
                        yt[nc2][i] = fmaf(dt * 0.125f, Qt[nc2][i] + kv, yt[nc2][i]);
                        stv[nc2][i] = yt[nc2][i];
                    }
                }
            }
#pragma unroll
            for (int kc = 0; kc < 4; ++kc) {
                split2(stv[2 * kc][0], stv[2 * kc][1], Ah[kc][0], Al[kc][0]);
                split2(stv[2 * kc][2], stv[2 * kc][3], Ah[kc][1], Al[kc][1]);
                split2(stv[2 * kc + 1][0], stv[2 * kc + 1][1], Ah[kc][2], Al[kc][2]);
                split2(stv[2 * kc + 1][2], stv[2 * kc + 1][3], Ah[kc][3], Al[kc][3]);
            }
            if (m == 3) {  // fused emission from registers
#pragma unroll
                for (int nc2 = 0; nc2 < 8; ++nc2) {
                    float4 x0v = s->x0s[nc2][tid];
                    *(float4*)(obA + (size_t)j * 1024 + nc2 * 16) =
                        make_float4(x0v.x, yt[nc2][0], x0v.y, yt[nc2][1]);
                    *(float4*)(obB + (size_t)j * 1024 + nc2 * 16) =
                        make_float4(x0v.z, yt[nc2][2], x0v.w, yt[nc2][3]);
                }
            }
        }
    }
}

extern "C" void kernel_launch(void* const* d_in, const int* in_sizes, int n_in,
                              void* d_out, int out_size) {
    (void)in_sizes; (void)n_in; (void)out_size;
    cudaFuncSetAttribute(ode_kernel, cudaFuncAttributeMaxDynamicSharedMemorySize,
                         (int)sizeof(Smem));
    ode_kernel<<<96, NT, sizeof(Smem)>>>(
        (const float*)d_in[0], (const float*)d_in[1], (const float*)d_in[2],
        (const float*)d_in[3], (const float*)d_in[4], (const float*)d_in[5],
        (float*)d_out);
}